// round 8
// baseline (speedup 1.0000x reference)
#include <cuda_runtime.h>
#include <cuda_fp16.h>
#include <math.h>

#define B_DIM 16
#define N_DIM 196608
#define BPB   128      // reduce blocks per batch
#define TPB   256
#define NACC  27       // 21 sym H entries + 6 g entries
#define NPAIR (N_DIM / 2)
#define STRIDE (BPB * TPB)   // 32768; NPAIR/STRIDE == 3 exactly

// Fixed-slot partials: [value 0..26][batch 0..15][block 0..127]
__device__ float g_part[NACC * B_DIM * BPB];
// Unclipped delta_pose per batch (used by depth pass)
__device__ float g_dp[B_DIM * 6];
// last-block-per-batch counters (reset in-kernel each run)
__device__ unsigned int g_cnt[B_DIM];

#define SP ((size_t)B_DIM * N_DIM)
// half2 scratch: plane k holds (ih[2k], ih[2k+1]) per point
__device__ __align__(16) __half2 g_scrh[3 * B_DIM * N_DIM];
// fp32 scratch: inv*gd per point (dominant term, keep full precision)
__device__ __align__(16) float   g_scrf[B_DIM * N_DIM];

// ---- L2 cache-policy helpers (evict_last via cache_hint policy) -------------
__device__ __forceinline__ unsigned long long mk_policy_evl() {
    unsigned long long pol;
    asm("createpolicy.fractional.L2::evict_last.b64 %0, 1.0;" : "=l"(pol));
    return pol;
}
__device__ __forceinline__ void st_evl_b64(void* p, unsigned int x, unsigned int y,
                                           unsigned long long pol) {
    asm volatile("st.global.L2::cache_hint.v2.b32 [%0], {%1,%2}, %3;"
                 :: "l"(p), "r"(x), "r"(y), "l"(pol) : "memory");
}
__device__ __forceinline__ void st_evl_f2(void* p, float x, float y,
                                          unsigned long long pol) {
    asm volatile("st.global.L2::cache_hint.v2.f32 [%0], {%1,%2}, %3;"
                 :: "l"(p), "f"(x), "f"(y), "l"(pol) : "memory");
}

// per-pair input bundle (9 x float4, loaded streaming / evict-first)
struct PairData {
    float4 rv, wv, jdv, a0, a1, a2, a3, a4, a5;
};

__device__ __forceinline__ PairData load_pair(
    const float* __restrict__ r, const float* __restrict__ w,
    const float* __restrict__ Jp, const float* __restrict__ Jd, size_t p)
{
    PairData d;
    d.rv  = __ldcs((const float4*)(r  + 2 * p));
    d.wv  = __ldcs((const float4*)(w  + 2 * p));
    d.jdv = __ldcs((const float4*)(Jd + 2 * p));
    d.a0  = __ldcs((const float4*)(Jp + 12 * p));
    d.a1  = __ldcs((const float4*)(Jp + 12 * p + 4));
    d.a2  = __ldcs((const float4*)(Jp + 12 * p + 8));
    d.a3  = __ldcs((const float4*)(Jp + 12 * p + 12));
    d.a4  = __ldcs((const float4*)(Jp + 12 * p + 16));
    d.a5  = __ldcs((const float4*)(Jp + 12 * p + 20));
    return d;
}

__device__ __forceinline__ void process_pair(
    const PairData& d, size_t p, float lam, float* acc, unsigned long long pol)
{
    const float jpA[2][6] = {{d.a0.x, d.a0.y, d.a0.z, d.a0.w, d.a1.x, d.a1.y},
                             {d.a3.x, d.a3.y, d.a3.z, d.a3.w, d.a4.x, d.a4.y}};
    const float jpB[2][6] = {{d.a1.z, d.a1.w, d.a2.x, d.a2.y, d.a2.z, d.a2.w},
                             {d.a4.z, d.a4.w, d.a5.x, d.a5.y, d.a5.z, d.a5.w}};
    const float rx[2]  = {d.rv.x, d.rv.z};
    const float ry[2]  = {d.rv.y, d.rv.w};
    const float cf[2]  = {d.wv.x, d.wv.z};
    const float nlv[2] = {d.wv.y, d.wv.w};
    const float jdx[2] = {d.jdv.x, d.jdv.z};
    const float jdy[2] = {d.jdv.y, d.jdv.w};

    __half2 hs[3][2];
    float   fg[2];

#pragma unroll
    for (int k = 0; k < 2; k++) {
        const float conf = cf[k];
        float hpd[6];
#pragma unroll
        for (int i = 0; i < 6; i++)
            hpd[i] = conf * fmaf(jdx[k], jpA[k][i], jdy[k] * jpB[k][i]);

        const float hdd = conf * fmaf(jdx[k], jdx[k], jdy[k] * jdy[k]);
        const float gd  = conf * fmaf(jdx[k], rx[k], jdy[k] * ry[k]);
        const float inv = 1.0f / fmaxf(hdd + lam + nlv[k], 1e-4f);

        float cj0[6], cj1[6], ih[6];
#pragma unroll
        for (int i = 0; i < 6; i++) {
            cj0[i] = conf * jpA[k][i];
            cj1[i] = conf * jpB[k][i];
            ih[i]  = inv * hpd[i];
        }

        hs[0][k] = __floats2half2_rn(ih[0], ih[1]);
        hs[1][k] = __floats2half2_rn(ih[2], ih[3]);
        hs[2][k] = __floats2half2_rn(ih[4], ih[5]);
        fg[k]    = inv * gd;

        int idx = 0;
#pragma unroll
        for (int i = 0; i < 6; i++) {
#pragma unroll
            for (int j = i; j < 6; j++) {
                float t = acc[idx];
                t = fmaf(cj0[i], jpA[k][j], t);
                t = fmaf(cj1[i], jpB[k][j], t);
                t = fmaf(-ih[i], hpd[j], t);
                acc[idx++] = t;
            }
        }
#pragma unroll
        for (int i = 0; i < 6; i++) {
            float t = acc[21 + i];
            t = fmaf(cj0[i], rx[k], t);
            t = fmaf(cj1[i], ry[k], t);
            t = fmaf(-ih[i], gd, t);
            acc[21 + i] = t;
        }
    }

    // packed scratch stores, pinned in L2 with evict_last policy
#pragma unroll
    for (int kk = 0; kk < 3; kk++) {
        st_evl_b64(g_scrh + (size_t)kk * SP + p,
                   *(const unsigned int*)&hs[kk][0],
                   *(const unsigned int*)&hs[kk][1], pol);
    }
    st_evl_f2(g_scrf + p, fg[0], fg[1], pol);
}

// ---------------------------------------------------------------------------
// Kernel 1: fused reduction, 3 iterations fully unrolled with a 2-deep
//           load pipeline; tail: last block per batch reduces + fp32 LU solve.
// ---------------------------------------------------------------------------
__global__ void reduce_kernel(
    const float* __restrict__ r, const float* __restrict__ w,
    const float* __restrict__ Jp, const float* __restrict__ Jd,
    const float* __restrict__ lmbda, float* __restrict__ out_pose)
{
    const int b   = blockIdx.y;
    const int blk = blockIdx.x;
    const float lam = __ldg(lmbda + b);
    const unsigned long long pol = mk_policy_evl();

    float acc[NACC];
#pragma unroll
    for (int i = 0; i < NACC; i++) acc[i] = 0.f;

    const size_t base = (size_t)b * N_DIM;
    const int    q0   = blk * TPB + threadIdx.x;
    const size_t p0 = base + (size_t)q0 * 2;
    const size_t p1 = p0 + (size_t)STRIDE * 2;
    const size_t p2 = p1 + (size_t)STRIDE * 2;

    // software pipeline: >=18 loads in flight before first compute
    PairData d0 = load_pair(r, w, Jp, Jd, p0);
    PairData d1 = load_pair(r, w, Jp, Jd, p1);
    process_pair(d0, p0, lam, acc, pol);
    PairData d2 = load_pair(r, w, Jp, Jd, p2);
    process_pair(d1, p1, lam, acc, pol);
    process_pair(d2, p2, lam, acc, pol);

    // intra-warp tree reduce
#pragma unroll
    for (int off = 16; off; off >>= 1) {
#pragma unroll
        for (int i = 0; i < NACC; i++)
            acc[i] += __shfl_down_sync(0xFFFFFFFFu, acc[i], off);
    }

    __shared__ float sh[TPB / 32][NACC];
    const int wid  = threadIdx.x >> 5;
    const int lane = threadIdx.x & 31;
    if (lane == 0) {
#pragma unroll
        for (int i = 0; i < NACC; i++) sh[wid][i] = acc[i];
    }
    __syncthreads();

    if (threadIdx.x < NACC) {
        float s = 0.f;
#pragma unroll
        for (int wgi = 0; wgi < TPB / 32; wgi++) s += sh[wgi][threadIdx.x];
        g_part[threadIdx.x * (B_DIM * BPB) + b * BPB + blk] = s;
    }

    // ---- last block of this batch: final reduce + fp32 LU solve ----
    __threadfence();
    __shared__ unsigned int is_last;
    if (threadIdx.x == 0) {
        unsigned int prev = atomicAdd(&g_cnt[b], 1u);
        is_last = (prev == BPB - 1) ? 1u : 0u;
    }
    __syncthreads();
    if (!is_last) return;
    __threadfence();   // acquire: see all blocks' g_part writes

    __shared__ float red[NACC][8];
    __shared__ float sums[NACC];
    {
        const int v = threadIdx.x >> 3;
        const int s = threadIdx.x & 7;
        if (v < NACC) {
            const float* pp = g_part + v * (B_DIM * BPB) + b * BPB + s * 16;
            float t = 0.f;
#pragma unroll
            for (int i = 0; i < 16; i++) t += pp[i];
            red[v][s] = t;
        }
    }
    __syncthreads();
    if (threadIdx.x < NACC) {
        float t = 0.f;
#pragma unroll
        for (int s = 0; s < 8; s++) t += red[threadIdx.x][s];
        sums[threadIdx.x] = t;
    }
    __syncthreads();

    if (threadIdx.x == 0) {
        float M[6][6], gv[6], x[6];
        int idx = 0;
        for (int i = 0; i < 6; i++)
            for (int j = i; j < 6; j++) {
                const float v = sums[idx++];
                M[i][j] = v; M[j][i] = v;
            }
        const float dd = lam + 0.011f;
        for (int i = 0; i < 6; i++) M[i][i] += dd;
        for (int i = 0; i < 6; i++) gv[i] = sums[21 + i];

        for (int c = 0; c < 6; c++) {
            int piv = c; float mx = fabsf(M[c][c]);
            for (int rr = c + 1; rr < 6; rr++) {
                const float a = fabsf(M[rr][c]);
                if (a > mx) { mx = a; piv = rr; }
            }
            if (piv != c) {
                for (int j = 0; j < 6; j++) {
                    const float tmp = M[c][j]; M[c][j] = M[piv][j]; M[piv][j] = tmp;
                }
                const float tmp = gv[c]; gv[c] = gv[piv]; gv[piv] = tmp;
            }
            float d = M[c][c];
            if (d == 0.f) d = 1e-30f;
            const float invd = 1.0f / d;
            for (int rr = c + 1; rr < 6; rr++) {
                const float f = M[rr][c] * invd;
                for (int j = c; j < 6; j++) M[rr][j] -= f * M[c][j];
                gv[rr] -= f * gv[c];
            }
        }
        for (int i = 5; i >= 0; i--) {
            float s = gv[i];
            for (int j = i + 1; j < 6; j++) s -= M[i][j] * x[j];
            x[i] = s / M[i][i];
        }

        for (int i = 0; i < 6; i++) {
            g_dp[b * 6 + i] = x[i];                                   // unclipped
            out_pose[b * 6 + i] = fminf(fmaxf(x[i], -2.0f), 2.0f);    // clipped
        }
        g_cnt[b] = 0;   // reset for next graph replay
    }
}

// ---------------------------------------------------------------------------
// Kernel 2: depth = inv*gd - Sum_k (ih[k] . dp); 4 points per thread,
//           scratch reads expected to hit L2 (evict_last on store side).
// ---------------------------------------------------------------------------
__global__ void __launch_bounds__(TPB) depth_kernel(float* __restrict__ out_depth)
{
    const int b = blockIdx.y;
    const size_t p = (size_t)b * N_DIM +
                     ((size_t)blockIdx.x * TPB + threadIdx.x) * 4;

    const float4 f0 = *(const float4*)(g_scrf + p);
    const uint4 u0 = *(const uint4*)(g_scrh + 0 * SP + p);
    const uint4 u1 = *(const uint4*)(g_scrh + 1 * SP + p);
    const uint4 u2 = *(const uint4*)(g_scrh + 2 * SP + p);

    float2 dpp[3];
#pragma unroll
    for (int k = 0; k < 3; k++) {
        dpp[k].x = __ldg(g_dp + b * 6 + 2 * k);
        dpp[k].y = __ldg(g_dp + b * 6 + 2 * k + 1);
    }

    float res[4] = {f0.x, f0.y, f0.z, f0.w};
    const uint4 uu[3] = {u0, u1, u2};
#pragma unroll
    for (int k = 0; k < 3; k++) {
        const float2 q0 = __half22float2(*(const __half2*)&uu[k].x);
        const float2 q1 = __half22float2(*(const __half2*)&uu[k].y);
        const float2 q2 = __half22float2(*(const __half2*)&uu[k].z);
        const float2 q3 = __half22float2(*(const __half2*)&uu[k].w);
        res[0] = fmaf(-q0.x, dpp[k].x, fmaf(-q0.y, dpp[k].y, res[0]));
        res[1] = fmaf(-q1.x, dpp[k].x, fmaf(-q1.y, dpp[k].y, res[1]));
        res[2] = fmaf(-q2.x, dpp[k].x, fmaf(-q2.y, dpp[k].y, res[2]));
        res[3] = fmaf(-q3.x, dpp[k].x, fmaf(-q3.y, dpp[k].y, res[3]));
    }

    *(float4*)(out_depth + p) = make_float4(res[0], res[1], res[2], res[3]);
}

// ---------------------------------------------------------------------------
extern "C" void kernel_launch(void* const* d_in, const int* in_sizes, int n_in,
                              void* d_out, int out_size)
{
    const float* r   = (const float*)d_in[0];
    const float* w   = (const float*)d_in[1];
    const float* Jp  = (const float*)d_in[2];
    const float* Jd  = (const float*)d_in[3];
    const float* lam = (const float*)d_in[4];
    float* out = (float*)d_out;

    dim3 g1(BPB, B_DIM);
    reduce_kernel<<<g1, TPB>>>(r, w, Jp, Jd, lam, out);

    dim3 g2(N_DIM / (4 * TPB), B_DIM);
    depth_kernel<<<g2, TPB>>>(out + B_DIM * 6);
}

// round 9
// speedup vs baseline: 1.1288x; 1.1288x over previous
#include <cuda_runtime.h>
#include <cuda_fp16.h>
#include <math.h>

#define B_DIM 16
#define N_DIM 196608
#define BPB   128      // reduce blocks per batch
#define TPB   256
#define NACC  27       // 21 sym H entries + 6 g entries
#define NPAIR (N_DIM / 2)

// Fixed-slot partials: [value 0..26][batch 0..15][block 0..127]
__device__ float g_part[NACC * B_DIM * BPB];
// Unclipped delta_pose per batch (used by depth pass)
__device__ float g_dp[B_DIM * 6];
// last-block-per-batch counters (reset in-kernel each run)
__device__ unsigned int g_cnt[B_DIM];

#define SP ((size_t)B_DIM * N_DIM)
// half2 scratch: plane k holds (ih[2k], ih[2k+1]) per point
__device__ __align__(16) __half2 g_scrh[3 * B_DIM * N_DIM];
// fp32 scratch: inv*gd per point (dominant term, keep full precision)
__device__ __align__(16) float   g_scrf[B_DIM * N_DIM];

struct __align__(8) h2x2 { __half2 a, b; };

// ---------------------------------------------------------------------------
// Kernel 1: fused reduction (2 points/iter, 9 wide loads) + packed scratch
//           stores + last-block final reduce + fp32 LU solve per batch.
//           (R5 structure — plain loads/stores, simple grid-stride loop.)
// ---------------------------------------------------------------------------
__global__ void __launch_bounds__(TPB) reduce_kernel(
    const float* __restrict__ r, const float* __restrict__ w,
    const float* __restrict__ Jp, const float* __restrict__ Jd,
    const float* __restrict__ lmbda, float* __restrict__ out_pose)
{
    const int b   = blockIdx.y;
    const int blk = blockIdx.x;
    const float lam = __ldg(lmbda + b);

    float acc[NACC];
#pragma unroll
    for (int i = 0; i < NACC; i++) acc[i] = 0.f;

    const size_t base = (size_t)b * N_DIM;

    for (int q = blk * TPB + threadIdx.x; q < NPAIR; q += BPB * TPB) {
        const size_t p = base + (size_t)q * 2;   // first point of the pair

        // front-batched wide loads for BOTH points
        const float4 rv  = *(const float4*)(r  + 2 * p);  // r0x r0y r1x r1y
        const float4 wv  = *(const float4*)(w  + 2 * p);  // c0 nl0 c1 nl1
        const float4 jdv = *(const float4*)(Jd + 2 * p);  // d0x d0y d1x d1y
        const float4 a0 = *(const float4*)(Jp + 12 * p);
        const float4 a1 = *(const float4*)(Jp + 12 * p + 4);
        const float4 a2 = *(const float4*)(Jp + 12 * p + 8);
        const float4 a3 = *(const float4*)(Jp + 12 * p + 12);
        const float4 a4 = *(const float4*)(Jp + 12 * p + 16);
        const float4 a5 = *(const float4*)(Jp + 12 * p + 20);

        const float jpA[2][6] = {{a0.x, a0.y, a0.z, a0.w, a1.x, a1.y},
                                 {a3.x, a3.y, a3.z, a3.w, a4.x, a4.y}};
        const float jpB[2][6] = {{a1.z, a1.w, a2.x, a2.y, a2.z, a2.w},
                                 {a4.z, a4.w, a5.x, a5.y, a5.z, a5.w}};
        const float rx[2]  = {rv.x, rv.z};
        const float ry[2]  = {rv.y, rv.w};
        const float cf[2]  = {wv.x, wv.z};
        const float nlv[2] = {wv.y, wv.w};
        const float jdx[2] = {jdv.x, jdv.z};
        const float jdy[2] = {jdv.y, jdv.w};

        __half2 hs[3][2];
        float   fg[2];

#pragma unroll
        for (int k = 0; k < 2; k++) {
            const float conf = cf[k];
            float hpd[6];
#pragma unroll
            for (int i = 0; i < 6; i++)
                hpd[i] = conf * fmaf(jdx[k], jpA[k][i], jdy[k] * jpB[k][i]);

            const float hdd = conf * fmaf(jdx[k], jdx[k], jdy[k] * jdy[k]);
            const float gd  = conf * fmaf(jdx[k], rx[k], jdy[k] * ry[k]);
            const float inv = 1.0f / fmaxf(hdd + lam + nlv[k], 1e-4f);

            float cj0[6], cj1[6], ih[6];
#pragma unroll
            for (int i = 0; i < 6; i++) {
                cj0[i] = conf * jpA[k][i];
                cj1[i] = conf * jpB[k][i];
                ih[i]  = inv * hpd[i];
            }

            hs[0][k] = __floats2half2_rn(ih[0], ih[1]);
            hs[1][k] = __floats2half2_rn(ih[2], ih[3]);
            hs[2][k] = __floats2half2_rn(ih[4], ih[5]);
            fg[k]    = inv * gd;

            int idx = 0;
#pragma unroll
            for (int i = 0; i < 6; i++) {
#pragma unroll
                for (int j = i; j < 6; j++) {
                    float t = acc[idx];
                    t = fmaf(cj0[i], jpA[k][j], t);
                    t = fmaf(cj1[i], jpB[k][j], t);
                    t = fmaf(-ih[i], hpd[j], t);
                    acc[idx++] = t;
                }
            }
#pragma unroll
            for (int i = 0; i < 6; i++) {
                float t = acc[21 + i];
                t = fmaf(cj0[i], rx[k], t);
                t = fmaf(cj1[i], ry[k], t);
                t = fmaf(-ih[i], gd, t);
                acc[21 + i] = t;
            }
        }

        // packed, fully coalesced scratch stores (8 B each)
#pragma unroll
        for (int kk = 0; kk < 3; kk++) {
            h2x2 v; v.a = hs[kk][0]; v.b = hs[kk][1];
            *(h2x2*)(g_scrh + (size_t)kk * SP + p) = v;
        }
        *(float2*)(g_scrf + p) = make_float2(fg[0], fg[1]);
    }

    // intra-warp tree reduce
#pragma unroll
    for (int off = 16; off; off >>= 1) {
#pragma unroll
        for (int i = 0; i < NACC; i++)
            acc[i] += __shfl_down_sync(0xFFFFFFFFu, acc[i], off);
    }

    __shared__ float sh[TPB / 32][NACC];
    const int wid  = threadIdx.x >> 5;
    const int lane = threadIdx.x & 31;
    if (lane == 0) {
#pragma unroll
        for (int i = 0; i < NACC; i++) sh[wid][i] = acc[i];
    }
    __syncthreads();

    if (threadIdx.x < NACC) {
        float s = 0.f;
#pragma unroll
        for (int wgi = 0; wgi < TPB / 32; wgi++) s += sh[wgi][threadIdx.x];
        g_part[threadIdx.x * (B_DIM * BPB) + b * BPB + blk] = s;
    }

    // ---- last block of this batch: final reduce + fp32 LU solve ----
    __threadfence();
    __shared__ unsigned int is_last;
    if (threadIdx.x == 0) {
        unsigned int prev = atomicAdd(&g_cnt[b], 1u);
        is_last = (prev == BPB - 1) ? 1u : 0u;
    }
    __syncthreads();
    if (!is_last) return;
    __threadfence();   // acquire: see all blocks' g_part writes

    __shared__ float red[NACC][8];
    __shared__ float sums[NACC];
    {
        const int v = threadIdx.x >> 3;
        const int s = threadIdx.x & 7;
        if (v < NACC) {
            const float* pp = g_part + v * (B_DIM * BPB) + b * BPB + s * 16;
            float t = 0.f;
#pragma unroll
            for (int i = 0; i < 16; i++) t += pp[i];
            red[v][s] = t;
        }
    }
    __syncthreads();
    if (threadIdx.x < NACC) {
        float t = 0.f;
#pragma unroll
        for (int s = 0; s < 8; s++) t += red[threadIdx.x][s];
        sums[threadIdx.x] = t;
    }
    __syncthreads();

    if (threadIdx.x == 0) {
        float M[6][6], gv[6], x[6];
        int idx = 0;
        for (int i = 0; i < 6; i++)
            for (int j = i; j < 6; j++) {
                const float v = sums[idx++];
                M[i][j] = v; M[j][i] = v;
            }
        const float dd = lam + 0.011f;
        for (int i = 0; i < 6; i++) M[i][i] += dd;
        for (int i = 0; i < 6; i++) gv[i] = sums[21 + i];

        for (int c = 0; c < 6; c++) {
            int piv = c; float mx = fabsf(M[c][c]);
            for (int rr = c + 1; rr < 6; rr++) {
                const float a = fabsf(M[rr][c]);
                if (a > mx) { mx = a; piv = rr; }
            }
            if (piv != c) {
                for (int j = 0; j < 6; j++) {
                    const float tmp = M[c][j]; M[c][j] = M[piv][j]; M[piv][j] = tmp;
                }
                const float tmp = gv[c]; gv[c] = gv[piv]; gv[piv] = tmp;
            }
            float d = M[c][c];
            if (d == 0.f) d = 1e-30f;
            const float invd = 1.0f / d;
            for (int rr = c + 1; rr < 6; rr++) {
                const float f = M[rr][c] * invd;
                for (int j = c; j < 6; j++) M[rr][j] -= f * M[c][j];
                gv[rr] -= f * gv[c];
            }
        }
        for (int i = 5; i >= 0; i--) {
            float s = gv[i];
            for (int j = i + 1; j < 6; j++) s -= M[i][j] * x[j];
            x[i] = s / M[i][i];
        }

        for (int i = 0; i < 6; i++) {
            g_dp[b * 6 + i] = x[i];                                   // unclipped
            out_pose[b * 6 + i] = fminf(fmaxf(x[i], -2.0f), 2.0f);    // clipped
        }
        g_cnt[b] = 0;   // reset for next graph replay
    }
}

// ---------------------------------------------------------------------------
// Kernel 2: depth = inv*gd - Sum_k (ih[k] . dp); 16 points per thread,
//           16 front-batched 16B loads (MLP=16), 4 float4 stores.
// ---------------------------------------------------------------------------
__global__ void __launch_bounds__(TPB) depth_kernel(float* __restrict__ out_depth)
{
    const int b = blockIdx.y;
    const size_t p = (size_t)b * N_DIM +
                     ((size_t)blockIdx.x * TPB + threadIdx.x) * 16;

    // front-batch all loads: 4x float4 (inv*gd) + 3 planes x 4x uint4 (ih)
    float4 f[4];
    uint4  u[3][4];
#pragma unroll
    for (int j = 0; j < 4; j++)
        f[j] = *(const float4*)(g_scrf + p + 4 * j);
#pragma unroll
    for (int k = 0; k < 3; k++)
#pragma unroll
        for (int j = 0; j < 4; j++)
            u[k][j] = *(const uint4*)(g_scrh + (size_t)k * SP + p + 4 * j);

    float2 dpp[3];
#pragma unroll
    for (int k = 0; k < 3; k++) {
        dpp[k].x = __ldg(g_dp + b * 6 + 2 * k);
        dpp[k].y = __ldg(g_dp + b * 6 + 2 * k + 1);
    }

#pragma unroll
    for (int j = 0; j < 4; j++) {
        float res[4] = {f[j].x, f[j].y, f[j].z, f[j].w};
#pragma unroll
        for (int k = 0; k < 3; k++) {
            const float2 q0 = __half22float2(*(const __half2*)&u[k][j].x);
            const float2 q1 = __half22float2(*(const __half2*)&u[k][j].y);
            const float2 q2 = __half22float2(*(const __half2*)&u[k][j].z);
            const float2 q3 = __half22float2(*(const __half2*)&u[k][j].w);
            res[0] = fmaf(-q0.x, dpp[k].x, fmaf(-q0.y, dpp[k].y, res[0]));
            res[1] = fmaf(-q1.x, dpp[k].x, fmaf(-q1.y, dpp[k].y, res[1]));
            res[2] = fmaf(-q2.x, dpp[k].x, fmaf(-q2.y, dpp[k].y, res[2]));
            res[3] = fmaf(-q3.x, dpp[k].x, fmaf(-q3.y, dpp[k].y, res[3]));
        }
        *(float4*)(out_depth + p + 4 * j) =
            make_float4(res[0], res[1], res[2], res[3]);
    }
}

// ---------------------------------------------------------------------------
extern "C" void kernel_launch(void* const* d_in, const int* in_sizes, int n_in,
                              void* d_out, int out_size)
{
    const float* r   = (const float*)d_in[0];
    const float* w   = (const float*)d_in[1];
    const float* Jp  = (const float*)d_in[2];
    const float* Jd  = (const float*)d_in[3];
    const float* lam = (const float*)d_in[4];
    float* out = (float*)d_out;

    dim3 g1(BPB, B_DIM);
    reduce_kernel<<<g1, TPB>>>(r, w, Jp, Jd, lam, out);

    dim3 g2(N_DIM / (16 * TPB), B_DIM);
    depth_kernel<<<g2, TPB>>>(out + B_DIM * 6);
}

// round 10
// speedup vs baseline: 1.1595x; 1.0272x over previous
#include <cuda_runtime.h>
#include <cuda_fp16.h>
#include <math.h>

#define B_DIM 16
#define N_DIM 196608
#define BPB   128      // reduce blocks per batch
#define TPB   256
#define NACC  27       // 21 sym H entries + 6 g entries
#define NPAIR (N_DIM / 2)

// Fixed-slot partials: [value 0..26][batch 0..15][block 0..127]
__device__ float g_part[NACC * B_DIM * BPB];
// Unclipped delta_pose per batch (used by depth pass)
__device__ float g_dp[B_DIM * 6];
// last-block-per-batch counters (reset in-kernel each run)
__device__ unsigned int g_cnt[B_DIM];

#define SP ((size_t)B_DIM * N_DIM)
// half2 scratch: plane k holds (ih[2k], ih[2k+1]) per point
__device__ __align__(16) __half2 g_scrh[3 * B_DIM * N_DIM];
// fp32 scratch: inv*gd per point (dominant term, keep full precision)
__device__ __align__(16) float   g_scrf[B_DIM * N_DIM];

struct __align__(8) h2x2 { __half2 a, b; };

#define PAD7 7   // 7 float4 per pair in smem (6 used + 1 pad -> conflict-free)

// ---------------------------------------------------------------------------
// Kernel 1: fused reduction (2 points/iter) with warp-dense Jp staging via
//           shared memory; packed scratch stores; last-block reduce + solve.
// ---------------------------------------------------------------------------
__global__ void __launch_bounds__(TPB) reduce_kernel(
    const float* __restrict__ r, const float* __restrict__ w,
    const float* __restrict__ Jp, const float* __restrict__ Jd,
    const float* __restrict__ lmbda, float* __restrict__ out_pose)
{
    const int b   = blockIdx.y;
    const int blk = blockIdx.x;
    const float lam = __ldg(lmbda + b);

    __shared__ float4 sjp[TPB / 32][32 * PAD7];   // per-warp staging, padded

    const int wid  = threadIdx.x >> 5;
    const int lane = threadIdx.x & 31;

    float acc[NACC];
#pragma unroll
    for (int i = 0; i < NACC; i++) acc[i] = 0.f;

    const size_t base = (size_t)b * N_DIM;
    const float4* __restrict__ Jp4 = (const float4*)Jp;

    for (int q = blk * TPB + threadIdx.x; q < NPAIR; q += BPB * TPB) {
        const size_t p = base + (size_t)q * 2;   // first point of the pair

        // dense per-pair loads (16 B / thread stride) — already coalesced
        const float4 rv  = *(const float4*)(r  + 2 * p);  // r0x r0y r1x r1y
        const float4 wv  = *(const float4*)(w  + 2 * p);  // c0 nl0 c1 nl1
        const float4 jdv = *(const float4*)(Jd + 2 * p);  // d0x d0y d1x d1y

        // ---- warp-dense Jp staging ------------------------------------
        // warp's first pair this iteration:
        const int qw = q - lane;
        const size_t f4base = 3 * base + (size_t)qw * 6;   // float4 index
        __syncwarp();
#pragma unroll
        for (int j = 0; j < 6; j++) {
            const int idx = j * 32 + lane;            // 0..191 within region
            const float4 v = Jp4[f4base + idx];       // DENSE warp load
            sjp[wid][(idx / 6) * PAD7 + (idx % 6)] = v;
        }
        __syncwarp();
        const float4 a0 = sjp[wid][lane * PAD7 + 0];
        const float4 a1 = sjp[wid][lane * PAD7 + 1];
        const float4 a2 = sjp[wid][lane * PAD7 + 2];
        const float4 a3 = sjp[wid][lane * PAD7 + 3];
        const float4 a4 = sjp[wid][lane * PAD7 + 4];
        const float4 a5 = sjp[wid][lane * PAD7 + 5];
        // ----------------------------------------------------------------

        const float jpA[2][6] = {{a0.x, a0.y, a0.z, a0.w, a1.x, a1.y},
                                 {a3.x, a3.y, a3.z, a3.w, a4.x, a4.y}};
        const float jpB[2][6] = {{a1.z, a1.w, a2.x, a2.y, a2.z, a2.w},
                                 {a4.z, a4.w, a5.x, a5.y, a5.z, a5.w}};
        const float rx[2]  = {rv.x, rv.z};
        const float ry[2]  = {rv.y, rv.w};
        const float cf[2]  = {wv.x, wv.z};
        const float nlv[2] = {wv.y, wv.w};
        const float jdx[2] = {jdv.x, jdv.z};
        const float jdy[2] = {jdv.y, jdv.w};

        __half2 hs[3][2];
        float   fg[2];

#pragma unroll
        for (int k = 0; k < 2; k++) {
            const float conf = cf[k];
            float hpd[6];
#pragma unroll
            for (int i = 0; i < 6; i++)
                hpd[i] = conf * fmaf(jdx[k], jpA[k][i], jdy[k] * jpB[k][i]);

            const float hdd = conf * fmaf(jdx[k], jdx[k], jdy[k] * jdy[k]);
            const float gd  = conf * fmaf(jdx[k], rx[k], jdy[k] * ry[k]);
            const float inv = 1.0f / fmaxf(hdd + lam + nlv[k], 1e-4f);

            float cj0[6], cj1[6], ih[6];
#pragma unroll
            for (int i = 0; i < 6; i++) {
                cj0[i] = conf * jpA[k][i];
                cj1[i] = conf * jpB[k][i];
                ih[i]  = inv * hpd[i];
            }

            hs[0][k] = __floats2half2_rn(ih[0], ih[1]);
            hs[1][k] = __floats2half2_rn(ih[2], ih[3]);
            hs[2][k] = __floats2half2_rn(ih[4], ih[5]);
            fg[k]    = inv * gd;

            int idx = 0;
#pragma unroll
            for (int i = 0; i < 6; i++) {
#pragma unroll
                for (int j = i; j < 6; j++) {
                    float t = acc[idx];
                    t = fmaf(cj0[i], jpA[k][j], t);
                    t = fmaf(cj1[i], jpB[k][j], t);
                    t = fmaf(-ih[i], hpd[j], t);
                    acc[idx++] = t;
                }
            }
#pragma unroll
            for (int i = 0; i < 6; i++) {
                float t = acc[21 + i];
                t = fmaf(cj0[i], rx[k], t);
                t = fmaf(cj1[i], ry[k], t);
                t = fmaf(-ih[i], gd, t);
                acc[21 + i] = t;
            }
        }

        // packed, fully coalesced scratch stores (8 B each)
#pragma unroll
        for (int kk = 0; kk < 3; kk++) {
            h2x2 v; v.a = hs[kk][0]; v.b = hs[kk][1];
            *(h2x2*)(g_scrh + (size_t)kk * SP + p) = v;
        }
        *(float2*)(g_scrf + p) = make_float2(fg[0], fg[1]);
    }

    // intra-warp tree reduce
#pragma unroll
    for (int off = 16; off; off >>= 1) {
#pragma unroll
        for (int i = 0; i < NACC; i++)
            acc[i] += __shfl_down_sync(0xFFFFFFFFu, acc[i], off);
    }

    __shared__ float sh[TPB / 32][NACC];
    if (lane == 0) {
#pragma unroll
        for (int i = 0; i < NACC; i++) sh[wid][i] = acc[i];
    }
    __syncthreads();

    if (threadIdx.x < NACC) {
        float s = 0.f;
#pragma unroll
        for (int wgi = 0; wgi < TPB / 32; wgi++) s += sh[wgi][threadIdx.x];
        g_part[threadIdx.x * (B_DIM * BPB) + b * BPB + blk] = s;
    }

    // ---- last block of this batch: final reduce + fp32 LU solve ----
    __threadfence();
    __shared__ unsigned int is_last;
    if (threadIdx.x == 0) {
        unsigned int prev = atomicAdd(&g_cnt[b], 1u);
        is_last = (prev == BPB - 1) ? 1u : 0u;
    }
    __syncthreads();
    if (!is_last) return;
    __threadfence();   // acquire: see all blocks' g_part writes

    __shared__ float red[NACC][8];
    __shared__ float sums[NACC];
    {
        const int v = threadIdx.x >> 3;
        const int s = threadIdx.x & 7;
        if (v < NACC) {
            const float* pp = g_part + v * (B_DIM * BPB) + b * BPB + s * 16;
            float t = 0.f;
#pragma unroll
            for (int i = 0; i < 16; i++) t += pp[i];
            red[v][s] = t;
        }
    }
    __syncthreads();
    if (threadIdx.x < NACC) {
        float t = 0.f;
#pragma unroll
        for (int s = 0; s < 8; s++) t += red[threadIdx.x][s];
        sums[threadIdx.x] = t;
    }
    __syncthreads();

    if (threadIdx.x == 0) {
        float M[6][6], gv[6], x[6];
        int idx = 0;
        for (int i = 0; i < 6; i++)
            for (int j = i; j < 6; j++) {
                const float v = sums[idx++];
                M[i][j] = v; M[j][i] = v;
            }
        const float dd = lam + 0.011f;
        for (int i = 0; i < 6; i++) M[i][i] += dd;
        for (int i = 0; i < 6; i++) gv[i] = sums[21 + i];

        for (int c = 0; c < 6; c++) {
            int piv = c; float mx = fabsf(M[c][c]);
            for (int rr = c + 1; rr < 6; rr++) {
                const float a = fabsf(M[rr][c]);
                if (a > mx) { mx = a; piv = rr; }
            }
            if (piv != c) {
                for (int j = 0; j < 6; j++) {
                    const float tmp = M[c][j]; M[c][j] = M[piv][j]; M[piv][j] = tmp;
                }
                const float tmp = gv[c]; gv[c] = gv[piv]; gv[piv] = tmp;
            }
            float d = M[c][c];
            if (d == 0.f) d = 1e-30f;
            const float invd = 1.0f / d;
            for (int rr = c + 1; rr < 6; rr++) {
                const float f = M[rr][c] * invd;
                for (int j = c; j < 6; j++) M[rr][j] -= f * M[c][j];
                gv[rr] -= f * gv[c];
            }
        }
        for (int i = 5; i >= 0; i--) {
            float s = gv[i];
            for (int j = i + 1; j < 6; j++) s -= M[i][j] * x[j];
            x[i] = s / M[i][i];
        }

        for (int i = 0; i < 6; i++) {
            g_dp[b * 6 + i] = x[i];                                   // unclipped
            out_pose[b * 6 + i] = fminf(fmaxf(x[i], -2.0f), 2.0f);    // clipped
        }
        g_cnt[b] = 0;   // reset for next graph replay
    }
}

// ---------------------------------------------------------------------------
// Kernel 2: depth = inv*gd - Sum_k (ih[k] . dp); 4 points per thread,
//           all loads warp-dense (exact R5 version, known 11.4us).
// ---------------------------------------------------------------------------
__global__ void __launch_bounds__(TPB) depth_kernel(float* __restrict__ out_depth)
{
    const int b = blockIdx.y;
    const size_t p = (size_t)b * N_DIM +
                     ((size_t)blockIdx.x * TPB + threadIdx.x) * 4;

    const float4 f0 = *(const float4*)(g_scrf + p);
    const uint4 u0 = *(const uint4*)(g_scrh + 0 * SP + p);
    const uint4 u1 = *(const uint4*)(g_scrh + 1 * SP + p);
    const uint4 u2 = *(const uint4*)(g_scrh + 2 * SP + p);

    float2 dpp[3];
#pragma unroll
    for (int k = 0; k < 3; k++) {
        dpp[k].x = __ldg(g_dp + b * 6 + 2 * k);
        dpp[k].y = __ldg(g_dp + b * 6 + 2 * k + 1);
    }

    float res[4] = {f0.x, f0.y, f0.z, f0.w};
    const uint4 uu[3] = {u0, u1, u2};
#pragma unroll
    for (int k = 0; k < 3; k++) {
        const float2 q0 = __half22float2(*(const __half2*)&uu[k].x);
        const float2 q1 = __half22float2(*(const __half2*)&uu[k].y);
        const float2 q2 = __half22float2(*(const __half2*)&uu[k].z);
        const float2 q3 = __half22float2(*(const __half2*)&uu[k].w);
        res[0] = fmaf(-q0.x, dpp[k].x, fmaf(-q0.y, dpp[k].y, res[0]));
        res[1] = fmaf(-q1.x, dpp[k].x, fmaf(-q1.y, dpp[k].y, res[1]));
        res[2] = fmaf(-q2.x, dpp[k].x, fmaf(-q2.y, dpp[k].y, res[2]));
        res[3] = fmaf(-q3.x, dpp[k].x, fmaf(-q3.y, dpp[k].y, res[3]));
    }

    *(float4*)(out_depth + p) = make_float4(res[0], res[1], res[2], res[3]);
}

// ---------------------------------------------------------------------------
extern "C" void kernel_launch(void* const* d_in, const int* in_sizes, int n_in,
                              void* d_out, int out_size)
{
    const float* r   = (const float*)d_in[0];
    const float* w   = (const float*)d_in[1];
    const float* Jp  = (const float*)d_in[2];
    const float* Jd  = (const float*)d_in[3];
    const float* lam = (const float*)d_in[4];
    float* out = (float*)d_out;

    dim3 g1(BPB, B_DIM);
    reduce_kernel<<<g1, TPB>>>(r, w, Jp, Jd, lam, out);

    dim3 g2(N_DIM / (4 * TPB), B_DIM);
    depth_kernel<<<g2, TPB>>>(out + B_DIM * 6);
}

// round 11
// speedup vs baseline: 1.3396x; 1.1554x over previous
#include <cuda_runtime.h>
#include <cuda_fp16.h>
#include <math.h>

#define B_DIM  16
#define N_DIM  196608
#define TPB    256
#define NSLICE 18                 // blocks per batch
#define GRID   (B_DIM * NSLICE)   // 288 blocks, all resident (>=2/SM guaranteed)
#define NACC   27                 // 21 sym H entries + 6 g entries
#define NPAIR  (N_DIM / 2)
#define QPB    (N_DIM / 4)        // depth quads per batch = 49152
#define QTOT   (B_DIM * QPB)      // 786432

// Fixed-slot partials: [value 0..26][batch][slice]
__device__ float g_part[NACC * B_DIM * NSLICE];
// Unclipped delta_pose per batch
__device__ float g_dp[B_DIM * 6];

// grid barrier state (generation is monotonic across graph replays)
__device__ unsigned int g_bar_cnt = 0;
__device__ volatile unsigned int g_bar_gen = 0;

#define SP ((size_t)B_DIM * N_DIM)
// half2 scratch: plane k holds (ih[2k], ih[2k+1]) per point
__device__ __align__(16) __half2 g_scrh[3 * B_DIM * N_DIM];
// fp32 scratch: inv*gd per point
__device__ __align__(16) float   g_scrf[B_DIM * N_DIM];

struct __align__(8) h2x2 { __half2 a, b; };

// ---------------------------------------------------------------------------
// Deadlock-free grid barrier: every block reads gen BEFORE arriving; the
// 288th arriver resets the counter and bumps gen. Monotonic gen -> safe
// across graph replays. All blocks resident by construction (GRID=288,
// launch_bounds(256,2) -> capacity >= 296).
// ---------------------------------------------------------------------------
__device__ __forceinline__ void grid_barrier()
{
    __syncthreads();
    if (threadIdx.x == 0) {
        const unsigned int my = g_bar_gen;   // volatile read, before arrive
        __threadfence();
        const unsigned int prev = atomicAdd(&g_bar_cnt, 1u);
        if (prev == GRID - 1) {
            g_bar_cnt = 0;
            __threadfence();
            g_bar_gen = my + 1;              // release
        } else {
            while (g_bar_gen == my) { __nanosleep(64); }
        }
        __threadfence();
    }
    __syncthreads();
}

// ---------------------------------------------------------------------------
// Single fused kernel: reduce -> barrier -> solve -> barrier -> depth
// ---------------------------------------------------------------------------
__global__ void __launch_bounds__(TPB, 2) dba_kernel(
    const float* __restrict__ r, const float* __restrict__ w,
    const float* __restrict__ Jp, const float* __restrict__ Jd,
    const float* __restrict__ lmbda, float* __restrict__ out)
{
    const int b     = blockIdx.x / NSLICE;
    const int slice = blockIdx.x % NSLICE;
    const float lam = __ldg(lmbda + b);

    float* __restrict__ out_pose  = out;
    float* __restrict__ out_depth = out + B_DIM * 6;

    // ===================== Phase 1: streaming reduction =====================
    float acc[NACC];
#pragma unroll
    for (int i = 0; i < NACC; i++) acc[i] = 0.f;

    const size_t base = (size_t)b * N_DIM;

    for (int q = slice * TPB + threadIdx.x; q < NPAIR; q += NSLICE * TPB) {
        const size_t p = base + (size_t)q * 2;   // first point of the pair

        const float4 rv  = *(const float4*)(r  + 2 * p);
        const float4 wv  = *(const float4*)(w  + 2 * p);
        const float4 jdv = *(const float4*)(Jd + 2 * p);
        const float4 a0 = *(const float4*)(Jp + 12 * p);
        const float4 a1 = *(const float4*)(Jp + 12 * p + 4);
        const float4 a2 = *(const float4*)(Jp + 12 * p + 8);
        const float4 a3 = *(const float4*)(Jp + 12 * p + 12);
        const float4 a4 = *(const float4*)(Jp + 12 * p + 16);
        const float4 a5 = *(const float4*)(Jp + 12 * p + 20);

        const float jpA[2][6] = {{a0.x, a0.y, a0.z, a0.w, a1.x, a1.y},
                                 {a3.x, a3.y, a3.z, a3.w, a4.x, a4.y}};
        const float jpB[2][6] = {{a1.z, a1.w, a2.x, a2.y, a2.z, a2.w},
                                 {a4.z, a4.w, a5.x, a5.y, a5.z, a5.w}};
        const float rx[2]  = {rv.x, rv.z};
        const float ry[2]  = {rv.y, rv.w};
        const float cf[2]  = {wv.x, wv.z};
        const float nlv[2] = {wv.y, wv.w};
        const float jdx[2] = {jdv.x, jdv.z};
        const float jdy[2] = {jdv.y, jdv.w};

        __half2 hs[3][2];
        float   fg[2];

#pragma unroll
        for (int k = 0; k < 2; k++) {
            const float conf = cf[k];
            float hpd[6];
#pragma unroll
            for (int i = 0; i < 6; i++)
                hpd[i] = conf * fmaf(jdx[k], jpA[k][i], jdy[k] * jpB[k][i]);

            const float hdd = conf * fmaf(jdx[k], jdx[k], jdy[k] * jdy[k]);
            const float gd  = conf * fmaf(jdx[k], rx[k], jdy[k] * ry[k]);
            const float inv = 1.0f / fmaxf(hdd + lam + nlv[k], 1e-4f);

            float cj0[6], cj1[6], ih[6];
#pragma unroll
            for (int i = 0; i < 6; i++) {
                cj0[i] = conf * jpA[k][i];
                cj1[i] = conf * jpB[k][i];
                ih[i]  = inv * hpd[i];
            }

            hs[0][k] = __floats2half2_rn(ih[0], ih[1]);
            hs[1][k] = __floats2half2_rn(ih[2], ih[3]);
            hs[2][k] = __floats2half2_rn(ih[4], ih[5]);
            fg[k]    = inv * gd;

            int idx = 0;
#pragma unroll
            for (int i = 0; i < 6; i++) {
#pragma unroll
                for (int j = i; j < 6; j++) {
                    float t = acc[idx];
                    t = fmaf(cj0[i], jpA[k][j], t);
                    t = fmaf(cj1[i], jpB[k][j], t);
                    t = fmaf(-ih[i], hpd[j], t);
                    acc[idx++] = t;
                }
            }
#pragma unroll
            for (int i = 0; i < 6; i++) {
                float t = acc[21 + i];
                t = fmaf(cj0[i], rx[k], t);
                t = fmaf(cj1[i], ry[k], t);
                t = fmaf(-ih[i], gd, t);
                acc[21 + i] = t;
            }
        }

        // packed, coalesced scratch stores (8 B each)
#pragma unroll
        for (int kk = 0; kk < 3; kk++) {
            h2x2 v; v.a = hs[kk][0]; v.b = hs[kk][1];
            *(h2x2*)(g_scrh + (size_t)kk * SP + p) = v;
        }
        *(float2*)(g_scrf + p) = make_float2(fg[0], fg[1]);
    }

    // block-level reduce
#pragma unroll
    for (int off = 16; off; off >>= 1) {
#pragma unroll
        for (int i = 0; i < NACC; i++)
            acc[i] += __shfl_down_sync(0xFFFFFFFFu, acc[i], off);
    }

    __shared__ float sh[TPB / 32][NACC];
    const int wid  = threadIdx.x >> 5;
    const int lane = threadIdx.x & 31;
    if (lane == 0) {
#pragma unroll
        for (int i = 0; i < NACC; i++) sh[wid][i] = acc[i];
    }
    __syncthreads();

    if (threadIdx.x < NACC) {
        float s = 0.f;
#pragma unroll
        for (int wgi = 0; wgi < TPB / 32; wgi++) s += sh[wgi][threadIdx.x];
        g_part[threadIdx.x * (B_DIM * NSLICE) + b * NSLICE + slice] = s;
    }

    grid_barrier();

    // ===================== Phase 2: per-batch solve =========================
    if (slice == 0) {
        __shared__ float sums[NACC];
        if (threadIdx.x < NACC) {
            const float* pp = g_part + threadIdx.x * (B_DIM * NSLICE) + b * NSLICE;
            float t = 0.f;
#pragma unroll
            for (int i = 0; i < NSLICE; i++) t += pp[i];
            sums[threadIdx.x] = t;
        }
        __syncthreads();

        if (threadIdx.x == 0) {
            float M[6][6], gv[6], x[6];
            int idx = 0;
            for (int i = 0; i < 6; i++)
                for (int j = i; j < 6; j++) {
                    const float v = sums[idx++];
                    M[i][j] = v; M[j][i] = v;
                }
            const float dd = lam + 0.011f;
            for (int i = 0; i < 6; i++) M[i][i] += dd;
            for (int i = 0; i < 6; i++) gv[i] = sums[21 + i];

            for (int c = 0; c < 6; c++) {
                int piv = c; float mx = fabsf(M[c][c]);
                for (int rr = c + 1; rr < 6; rr++) {
                    const float a = fabsf(M[rr][c]);
                    if (a > mx) { mx = a; piv = rr; }
                }
                if (piv != c) {
                    for (int j = 0; j < 6; j++) {
                        const float tmp = M[c][j]; M[c][j] = M[piv][j]; M[piv][j] = tmp;
                    }
                    const float tmp = gv[c]; gv[c] = gv[piv]; gv[piv] = tmp;
                }
                float d = M[c][c];
                if (d == 0.f) d = 1e-30f;
                const float invd = 1.0f / d;
                for (int rr = c + 1; rr < 6; rr++) {
                    const float f = M[rr][c] * invd;
                    for (int j = c; j < 6; j++) M[rr][j] -= f * M[c][j];
                    gv[rr] -= f * gv[c];
                }
            }
            for (int i = 5; i >= 0; i--) {
                float s = gv[i];
                for (int j = i + 1; j < 6; j++) s -= M[i][j] * x[j];
                x[i] = s / M[i][i];
            }

            for (int i = 0; i < 6; i++) {
                g_dp[b * 6 + i] = x[i];                                 // unclipped
                out_pose[b * 6 + i] = fminf(fmaxf(x[i], -2.0f), 2.0f);  // clipped
            }
        }
    }

    grid_barrier();

    // ===================== Phase 3: depth ==================================
    const int gtid = blockIdx.x * TPB + threadIdx.x;
    for (int i = gtid; i < QTOT; i += GRID * TPB) {
        const int b2 = i / QPB;
        const size_t p = (size_t)b2 * N_DIM + (size_t)(i - b2 * QPB) * 4;

        const float4 f0 = *(const float4*)(g_scrf + p);
        const uint4 u0 = *(const uint4*)(g_scrh + 0 * SP + p);
        const uint4 u1 = *(const uint4*)(g_scrh + 1 * SP + p);
        const uint4 u2 = *(const uint4*)(g_scrh + 2 * SP + p);

        float2 dpp[3];
#pragma unroll
        for (int k = 0; k < 3; k++) {
            dpp[k].x = __ldg(g_dp + b2 * 6 + 2 * k);
            dpp[k].y = __ldg(g_dp + b2 * 6 + 2 * k + 1);
        }

        float res[4] = {f0.x, f0.y, f0.z, f0.w};
        const uint4 uu[3] = {u0, u1, u2};
#pragma unroll
        for (int k = 0; k < 3; k++) {
            const float2 q0 = __half22float2(*(const __half2*)&uu[k].x);
            const float2 q1 = __half22float2(*(const __half2*)&uu[k].y);
            const float2 q2 = __half22float2(*(const __half2*)&uu[k].z);
            const float2 q3 = __half22float2(*(const __half2*)&uu[k].w);
            res[0] = fmaf(-q0.x, dpp[k].x, fmaf(-q0.y, dpp[k].y, res[0]));
            res[1] = fmaf(-q1.x, dpp[k].x, fmaf(-q1.y, dpp[k].y, res[1]));
            res[2] = fmaf(-q2.x, dpp[k].x, fmaf(-q2.y, dpp[k].y, res[2]));
            res[3] = fmaf(-q3.x, dpp[k].x, fmaf(-q3.y, dpp[k].y, res[3]));
        }

        *(float4*)(out_depth + p) = make_float4(res[0], res[1], res[2], res[3]);
    }
}

// ---------------------------------------------------------------------------
extern "C" void kernel_launch(void* const* d_in, const int* in_sizes, int n_in,
                              void* d_out, int out_size)
{
    const float* r   = (const float*)d_in[0];
    const float* w   = (const float*)d_in[1];
    const float* Jp  = (const float*)d_in[2];
    const float* Jd  = (const float*)d_in[3];
    const float* lam = (const float*)d_in[4];
    float* out = (float*)d_out;

    dba_kernel<<<GRID, TPB>>>(r, w, Jp, Jd, lam, out);
}

// round 12
// speedup vs baseline: 1.3909x; 1.0383x over previous
#include <cuda_runtime.h>
#include <cuda_fp16.h>
#include <math.h>

#define B_DIM  16
#define N_DIM  196608
#define TPB    256
#define NSLICE 18                 // blocks per batch
#define GRID   (B_DIM * NSLICE)   // 288 blocks, all resident (2/SM guaranteed)
#define NACC   27                 // 21 sym H entries + 6 g entries
#define NPAIR  (N_DIM / 2)
#define QPB    (N_DIM / 4)        // depth quads per batch = 49152

// Fixed-slot partials: [value 0..26][batch][slice]
__device__ float g_part[NACC * B_DIM * NSLICE];

// per-batch barrier state (generation monotonic across graph replays)
__device__ unsigned int g_bcnt[B_DIM];
__device__ volatile unsigned int g_bgen[B_DIM];

#define SP ((size_t)B_DIM * N_DIM)
// half2 scratch: plane k holds (ih[2k], ih[2k+1]) per point
__device__ __align__(16) __half2 g_scrh[3 * B_DIM * N_DIM];
// fp32 scratch: inv*gd per point
__device__ __align__(16) float   g_scrf[B_DIM * N_DIM];

struct __align__(8) h2x2 { __half2 a, b; };

// ---------------------------------------------------------------------------
// Per-batch barrier: only the NSLICE blocks of one batch synchronize.
// Generation read BEFORE arrive; last arriver resets count and bumps gen.
// All blocks resident (GRID=288, launch_bounds(256,2)) -> no deadlock.
// ---------------------------------------------------------------------------
__device__ __forceinline__ void batch_barrier(int b)
{
    __syncthreads();
    if (threadIdx.x == 0) {
        const unsigned int my = g_bgen[b];   // volatile read, before arrive
        __threadfence();
        const unsigned int prev = atomicAdd(&g_bcnt[b], 1u);
        if (prev == NSLICE - 1) {
            g_bcnt[b] = 0;
            __threadfence();
            g_bgen[b] = my + 1;              // release
        } else {
            while (g_bgen[b] == my) { __nanosleep(64); }
        }
        __threadfence();
    }
    __syncthreads();
}

// ---------------------------------------------------------------------------
// Single fused kernel: reduce -> per-batch barrier -> redundant solve -> depth
// ---------------------------------------------------------------------------
__global__ void __launch_bounds__(TPB, 2) dba_kernel(
    const float* __restrict__ r, const float* __restrict__ w,
    const float* __restrict__ Jp, const float* __restrict__ Jd,
    const float* __restrict__ lmbda, float* __restrict__ out)
{
    const int b     = blockIdx.x / NSLICE;
    const int slice = blockIdx.x % NSLICE;
    const float lam = __ldg(lmbda + b);

    float* __restrict__ out_pose  = out;
    float* __restrict__ out_depth = out + B_DIM * 6;

    // ===================== Phase 1: streaming reduction =====================
    float acc[NACC];
#pragma unroll
    for (int i = 0; i < NACC; i++) acc[i] = 0.f;

    const size_t base = (size_t)b * N_DIM;

    for (int q = slice * TPB + threadIdx.x; q < NPAIR; q += NSLICE * TPB) {
        const size_t p = base + (size_t)q * 2;   // first point of the pair

        const float4 rv  = *(const float4*)(r  + 2 * p);
        const float4 wv  = *(const float4*)(w  + 2 * p);
        const float4 jdv = *(const float4*)(Jd + 2 * p);
        const float4 a0 = *(const float4*)(Jp + 12 * p);
        const float4 a1 = *(const float4*)(Jp + 12 * p + 4);
        const float4 a2 = *(const float4*)(Jp + 12 * p + 8);
        const float4 a3 = *(const float4*)(Jp + 12 * p + 12);
        const float4 a4 = *(const float4*)(Jp + 12 * p + 16);
        const float4 a5 = *(const float4*)(Jp + 12 * p + 20);

        const float jpA[2][6] = {{a0.x, a0.y, a0.z, a0.w, a1.x, a1.y},
                                 {a3.x, a3.y, a3.z, a3.w, a4.x, a4.y}};
        const float jpB[2][6] = {{a1.z, a1.w, a2.x, a2.y, a2.z, a2.w},
                                 {a4.z, a4.w, a5.x, a5.y, a5.z, a5.w}};
        const float rx[2]  = {rv.x, rv.z};
        const float ry[2]  = {rv.y, rv.w};
        const float cf[2]  = {wv.x, wv.z};
        const float nlv[2] = {wv.y, wv.w};
        const float jdx[2] = {jdv.x, jdv.z};
        const float jdy[2] = {jdv.y, jdv.w};

        __half2 hs[3][2];
        float   fg[2];

#pragma unroll
        for (int k = 0; k < 2; k++) {
            const float conf = cf[k];
            float hpd[6];
#pragma unroll
            for (int i = 0; i < 6; i++)
                hpd[i] = conf * fmaf(jdx[k], jpA[k][i], jdy[k] * jpB[k][i]);

            const float hdd = conf * fmaf(jdx[k], jdx[k], jdy[k] * jdy[k]);
            const float gd  = conf * fmaf(jdx[k], rx[k], jdy[k] * ry[k]);
            const float inv = 1.0f / fmaxf(hdd + lam + nlv[k], 1e-4f);

            float cj0[6], cj1[6], ih[6];
#pragma unroll
            for (int i = 0; i < 6; i++) {
                cj0[i] = conf * jpA[k][i];
                cj1[i] = conf * jpB[k][i];
                ih[i]  = inv * hpd[i];
            }

            hs[0][k] = __floats2half2_rn(ih[0], ih[1]);
            hs[1][k] = __floats2half2_rn(ih[2], ih[3]);
            hs[2][k] = __floats2half2_rn(ih[4], ih[5]);
            fg[k]    = inv * gd;

            int idx = 0;
#pragma unroll
            for (int i = 0; i < 6; i++) {
#pragma unroll
                for (int j = i; j < 6; j++) {
                    float t = acc[idx];
                    t = fmaf(cj0[i], jpA[k][j], t);
                    t = fmaf(cj1[i], jpB[k][j], t);
                    t = fmaf(-ih[i], hpd[j], t);
                    acc[idx++] = t;
                }
            }
#pragma unroll
            for (int i = 0; i < 6; i++) {
                float t = acc[21 + i];
                t = fmaf(cj0[i], rx[k], t);
                t = fmaf(cj1[i], ry[k], t);
                t = fmaf(-ih[i], gd, t);
                acc[21 + i] = t;
            }
        }

        // packed, coalesced scratch stores (8 B each)
#pragma unroll
        for (int kk = 0; kk < 3; kk++) {
            h2x2 v; v.a = hs[kk][0]; v.b = hs[kk][1];
            *(h2x2*)(g_scrh + (size_t)kk * SP + p) = v;
        }
        *(float2*)(g_scrf + p) = make_float2(fg[0], fg[1]);
    }

    // block-level reduce
#pragma unroll
    for (int off = 16; off; off >>= 1) {
#pragma unroll
        for (int i = 0; i < NACC; i++)
            acc[i] += __shfl_down_sync(0xFFFFFFFFu, acc[i], off);
    }

    __shared__ float sh[TPB / 32][NACC];
    const int wid  = threadIdx.x >> 5;
    const int lane = threadIdx.x & 31;
    if (lane == 0) {
#pragma unroll
        for (int i = 0; i < NACC; i++) sh[wid][i] = acc[i];
    }
    __syncthreads();

    if (threadIdx.x < NACC) {
        float s = 0.f;
#pragma unroll
        for (int wgi = 0; wgi < TPB / 32; wgi++) s += sh[wgi][threadIdx.x];
        g_part[threadIdx.x * (B_DIM * NSLICE) + b * NSLICE + slice] = s;
    }

    batch_barrier(b);

    // ========== Phase 2: redundant per-block final reduce + LU solve ========
    __shared__ float sums[NACC];
    __shared__ float dpsh[6];
    if (threadIdx.x < NACC) {
        const float* pp = g_part + threadIdx.x * (B_DIM * NSLICE) + b * NSLICE;
        float t = 0.f;
#pragma unroll
        for (int i = 0; i < NSLICE; i++) t += pp[i];
        sums[threadIdx.x] = t;
    }
    __syncthreads();

    if (threadIdx.x == 0) {
        float M[6][6], gv[6], x[6];
        int idx = 0;
        for (int i = 0; i < 6; i++)
            for (int j = i; j < 6; j++) {
                const float v = sums[idx++];
                M[i][j] = v; M[j][i] = v;
            }
        const float dd = lam + 0.011f;
        for (int i = 0; i < 6; i++) M[i][i] += dd;
        for (int i = 0; i < 6; i++) gv[i] = sums[21 + i];

        for (int c = 0; c < 6; c++) {
            int piv = c; float mx = fabsf(M[c][c]);
            for (int rr = c + 1; rr < 6; rr++) {
                const float a = fabsf(M[rr][c]);
                if (a > mx) { mx = a; piv = rr; }
            }
            if (piv != c) {
                for (int j = 0; j < 6; j++) {
                    const float tmp = M[c][j]; M[c][j] = M[piv][j]; M[piv][j] = tmp;
                }
                const float tmp = gv[c]; gv[c] = gv[piv]; gv[piv] = tmp;
            }
            float d = M[c][c];
            if (d == 0.f) d = 1e-30f;
            const float invd = 1.0f / d;
            for (int rr = c + 1; rr < 6; rr++) {
                const float f = M[rr][c] * invd;
                for (int j = c; j < 6; j++) M[rr][j] -= f * M[c][j];
                gv[rr] -= f * gv[c];
            }
        }
        for (int i = 5; i >= 0; i--) {
            float s = gv[i];
            for (int j = i + 1; j < 6; j++) s -= M[i][j] * x[j];
            x[i] = s / M[i][i];
        }

#pragma unroll
        for (int i = 0; i < 6; i++) dpsh[i] = x[i];   // unclipped, for depth
        if (slice == 0) {
            for (int i = 0; i < 6; i++)
                out_pose[b * 6 + i] = fminf(fmaxf(x[i], -2.0f), 2.0f);
        }
    }
    __syncthreads();

    float2 dpp[3];
#pragma unroll
    for (int k = 0; k < 3; k++) {
        dpp[k].x = dpsh[2 * k];
        dpp[k].y = dpsh[2 * k + 1];
    }

    // ===================== Phase 3: depth (own batch only) ==================
    for (int i = slice * TPB + threadIdx.x; i < QPB; i += NSLICE * TPB) {
        const size_t p = base + (size_t)i * 4;

        const float4 f0 = *(const float4*)(g_scrf + p);
        const uint4 u0 = *(const uint4*)(g_scrh + 0 * SP + p);
        const uint4 u1 = *(const uint4*)(g_scrh + 1 * SP + p);
        const uint4 u2 = *(const uint4*)(g_scrh + 2 * SP + p);

        float res[4] = {f0.x, f0.y, f0.z, f0.w};
        const uint4 uu[3] = {u0, u1, u2};
#pragma unroll
        for (int k = 0; k < 3; k++) {
            const float2 q0 = __half22float2(*(const __half2*)&uu[k].x);
            const float2 q1 = __half22float2(*(const __half2*)&uu[k].y);
            const float2 q2 = __half22float2(*(const __half2*)&uu[k].z);
            const float2 q3 = __half22float2(*(const __half2*)&uu[k].w);
            res[0] = fmaf(-q0.x, dpp[k].x, fmaf(-q0.y, dpp[k].y, res[0]));
            res[1] = fmaf(-q1.x, dpp[k].x, fmaf(-q1.y, dpp[k].y, res[1]));
            res[2] = fmaf(-q2.x, dpp[k].x, fmaf(-q2.y, dpp[k].y, res[2]));
            res[3] = fmaf(-q3.x, dpp[k].x, fmaf(-q3.y, dpp[k].y, res[3]));
        }

        *(float4*)(out_depth + p) = make_float4(res[0], res[1], res[2], res[3]);
    }
}

// ---------------------------------------------------------------------------
extern "C" void kernel_launch(void* const* d_in, const int* in_sizes, int n_in,
                              void* d_out, int out_size)
{
    const float* r   = (const float*)d_in[0];
    const float* w   = (const float*)d_in[1];
    const float* Jp  = (const float*)d_in[2];
    const float* Jd  = (const float*)d_in[3];
    const float* lam = (const float*)d_in[4];
    float* out = (float*)d_out;

    dba_kernel<<<GRID, TPB>>>(r, w, Jp, Jd, lam, out);
}

// round 13
// speedup vs baseline: 1.4062x; 1.0110x over previous
#include <cuda_runtime.h>
#include <cuda_fp16.h>
#include <math.h>

#define B_DIM  16
#define N_DIM  196608
#define TPB    256
#define NSLICE 27                 // blocks per batch
#define GRID   (B_DIM * NSLICE)   // 432 blocks; 3 CTA/SM * 148 SM = 444 >= 432
#define NACC   27                 // 21 sym H entries + 6 g entries
#define QPB    (N_DIM / 4)        // depth quads per batch = 49152

// Fixed-slot partials: [value 0..26][batch][slice]
__device__ float g_part[NACC * B_DIM * NSLICE];

// per-batch barrier state (generation monotonic across graph replays)
__device__ unsigned int g_bcnt[B_DIM];
__device__ volatile unsigned int g_bgen[B_DIM];

#define SP ((size_t)B_DIM * N_DIM)
// half2 scratch: plane k holds (ih[2k], ih[2k+1]) per point
__device__ __align__(16) __half2 g_scrh[3 * B_DIM * N_DIM];
// fp32 scratch: inv*gd per point
__device__ __align__(16) float   g_scrf[B_DIM * N_DIM];

// ---------------------------------------------------------------------------
// Per-batch barrier: only the NSLICE blocks of one batch synchronize.
// Generation read BEFORE arrive; last arriver resets count and bumps gen.
// All blocks resident (GRID=432 <= 444 capacity) -> no deadlock.
// ---------------------------------------------------------------------------
__device__ __forceinline__ void batch_barrier(int b)
{
    __syncthreads();
    if (threadIdx.x == 0) {
        const unsigned int my = g_bgen[b];   // volatile read, before arrive
        __threadfence();
        const unsigned int prev = atomicAdd(&g_bcnt[b], 1u);
        if (prev == NSLICE - 1) {
            g_bcnt[b] = 0;
            __threadfence();
            g_bgen[b] = my + 1;              // release
        } else {
            while (g_bgen[b] == my) { __nanosleep(64); }
        }
        __threadfence();
    }
    __syncthreads();
}

// ---------------------------------------------------------------------------
// Single fused kernel: reduce -> per-batch barrier -> redundant solve -> depth
// Single-point inner loop (low reg pressure) to fit 3 CTAs/SM without spills.
// ---------------------------------------------------------------------------
__global__ void __launch_bounds__(TPB, 3) dba_kernel(
    const float* __restrict__ r, const float* __restrict__ w,
    const float* __restrict__ Jp, const float* __restrict__ Jd,
    const float* __restrict__ lmbda, float* __restrict__ out)
{
    const int b     = blockIdx.x / NSLICE;
    const int slice = blockIdx.x % NSLICE;
    const float lam = __ldg(lmbda + b);

    float* __restrict__ out_pose  = out;
    float* __restrict__ out_depth = out + B_DIM * 6;

    // ===================== Phase 1: streaming reduction =====================
    float acc[NACC];
#pragma unroll
    for (int i = 0; i < NACC; i++) acc[i] = 0.f;

    const size_t base = (size_t)b * N_DIM;

    for (int n = slice * TPB + threadIdx.x; n < N_DIM; n += NSLICE * TPB) {
        const size_t p = base + (size_t)n;
        const float2 rv = *(const float2*)(r  + 2 * p);
        const float2 wv = *(const float2*)(w  + 2 * p);
        const float2 jd = *(const float2*)(Jd + 2 * p);
        const float4 a0 = *(const float4*)(Jp + 12 * p);
        const float4 a1 = *(const float4*)(Jp + 12 * p + 4);
        const float4 a2 = *(const float4*)(Jp + 12 * p + 8);
        const float jp0[6] = {a0.x, a0.y, a0.z, a0.w, a1.x, a1.y};
        const float jp1[6] = {a1.z, a1.w, a2.x, a2.y, a2.z, a2.w};

        const float conf = wv.x;
        const float nl   = wv.y;

        float hpd[6];
#pragma unroll
        for (int i = 0; i < 6; i++)
            hpd[i] = conf * fmaf(jd.x, jp0[i], jd.y * jp1[i]);

        const float hdd = conf * fmaf(jd.x, jd.x, jd.y * jd.y);
        const float gd  = conf * fmaf(jd.x, rv.x, jd.y * rv.y);
        const float inv = 1.0f / fmaxf(hdd + lam + nl, 1e-4f);

        float cj0[6], cj1[6], ih[6];
#pragma unroll
        for (int i = 0; i < 6; i++) {
            cj0[i] = conf * jp0[i];
            cj1[i] = conf * jp1[i];
            ih[i]  = inv * hpd[i];
        }

        // scratch for depth pass (4 B per store, warp-dense)
        g_scrh[0 * SP + p] = __floats2half2_rn(ih[0], ih[1]);
        g_scrh[1 * SP + p] = __floats2half2_rn(ih[2], ih[3]);
        g_scrh[2 * SP + p] = __floats2half2_rn(ih[4], ih[5]);
        g_scrf[p] = inv * gd;

        int idx = 0;
#pragma unroll
        for (int i = 0; i < 6; i++) {
#pragma unroll
            for (int j = i; j < 6; j++) {
                float t = acc[idx];
                t = fmaf(cj0[i], jp0[j], t);
                t = fmaf(cj1[i], jp1[j], t);
                t = fmaf(-ih[i], hpd[j], t);
                acc[idx++] = t;
            }
        }
#pragma unroll
        for (int i = 0; i < 6; i++) {
            float t = acc[21 + i];
            t = fmaf(cj0[i], rv.x, t);
            t = fmaf(cj1[i], rv.y, t);
            t = fmaf(-ih[i], gd, t);
            acc[21 + i] = t;
        }
    }

    // block-level reduce
#pragma unroll
    for (int off = 16; off; off >>= 1) {
#pragma unroll
        for (int i = 0; i < NACC; i++)
            acc[i] += __shfl_down_sync(0xFFFFFFFFu, acc[i], off);
    }

    __shared__ float sh[TPB / 32][NACC];
    const int wid  = threadIdx.x >> 5;
    const int lane = threadIdx.x & 31;
    if (lane == 0) {
#pragma unroll
        for (int i = 0; i < NACC; i++) sh[wid][i] = acc[i];
    }
    __syncthreads();

    if (threadIdx.x < NACC) {
        float s = 0.f;
#pragma unroll
        for (int wgi = 0; wgi < TPB / 32; wgi++) s += sh[wgi][threadIdx.x];
        g_part[threadIdx.x * (B_DIM * NSLICE) + b * NSLICE + slice] = s;
    }

    batch_barrier(b);

    // ========== Phase 2: redundant per-block final reduce + LU solve ========
    __shared__ float sums[NACC];
    __shared__ float dpsh[6];
    if (threadIdx.x < NACC) {
        const float* pp = g_part + threadIdx.x * (B_DIM * NSLICE) + b * NSLICE;
        float t = 0.f;
#pragma unroll
        for (int i = 0; i < NSLICE; i++) t += pp[i];
        sums[threadIdx.x] = t;
    }
    __syncthreads();

    if (threadIdx.x == 0) {
        float M[6][6], gv[6], x[6];
        int idx = 0;
        for (int i = 0; i < 6; i++)
            for (int j = i; j < 6; j++) {
                const float v = sums[idx++];
                M[i][j] = v; M[j][i] = v;
            }
        const float dd = lam + 0.011f;
        for (int i = 0; i < 6; i++) M[i][i] += dd;
        for (int i = 0; i < 6; i++) gv[i] = sums[21 + i];

        for (int c = 0; c < 6; c++) {
            int piv = c; float mx = fabsf(M[c][c]);
            for (int rr = c + 1; rr < 6; rr++) {
                const float a = fabsf(M[rr][c]);
                if (a > mx) { mx = a; piv = rr; }
            }
            if (piv != c) {
                for (int j = 0; j < 6; j++) {
                    const float tmp = M[c][j]; M[c][j] = M[piv][j]; M[piv][j] = tmp;
                }
                const float tmp = gv[c]; gv[c] = gv[piv]; gv[piv] = tmp;
            }
            float d = M[c][c];
            if (d == 0.f) d = 1e-30f;
            const float invd = 1.0f / d;
            for (int rr = c + 1; rr < 6; rr++) {
                const float f = M[rr][c] * invd;
                for (int j = c; j < 6; j++) M[rr][j] -= f * M[c][j];
                gv[rr] -= f * gv[c];
            }
        }
        for (int i = 5; i >= 0; i--) {
            float s = gv[i];
            for (int j = i + 1; j < 6; j++) s -= M[i][j] * x[j];
            x[i] = s / M[i][i];
        }

#pragma unroll
        for (int i = 0; i < 6; i++) dpsh[i] = x[i];   // unclipped, for depth
        if (slice == 0) {
            for (int i = 0; i < 6; i++)
                out_pose[b * 6 + i] = fminf(fmaxf(x[i], -2.0f), 2.0f);
        }
    }
    __syncthreads();

    float2 dpp[3];
#pragma unroll
    for (int k = 0; k < 3; k++) {
        dpp[k].x = dpsh[2 * k];
        dpp[k].y = dpsh[2 * k + 1];
    }

    // ===================== Phase 3: depth (own batch only) ==================
    for (int i = slice * TPB + threadIdx.x; i < QPB; i += NSLICE * TPB) {
        const size_t p = base + (size_t)i * 4;

        const float4 f0 = *(const float4*)(g_scrf + p);
        const uint4 u0 = *(const uint4*)(g_scrh + 0 * SP + p);
        const uint4 u1 = *(const uint4*)(g_scrh + 1 * SP + p);
        const uint4 u2 = *(const uint4*)(g_scrh + 2 * SP + p);

        float res[4] = {f0.x, f0.y, f0.z, f0.w};
        const uint4 uu[3] = {u0, u1, u2};
#pragma unroll
        for (int k = 0; k < 3; k++) {
            const float2 q0 = __half22float2(*(const __half2*)&uu[k].x);
            const float2 q1 = __half22float2(*(const __half2*)&uu[k].y);
            const float2 q2 = __half22float2(*(const __half2*)&uu[k].z);
            const float2 q3 = __half22float2(*(const __half2*)&uu[k].w);
            res[0] = fmaf(-q0.x, dpp[k].x, fmaf(-q0.y, dpp[k].y, res[0]));
            res[1] = fmaf(-q1.x, dpp[k].x, fmaf(-q1.y, dpp[k].y, res[1]));
            res[2] = fmaf(-q2.x, dpp[k].x, fmaf(-q2.y, dpp[k].y, res[2]));
            res[3] = fmaf(-q3.x, dpp[k].x, fmaf(-q3.y, dpp[k].y, res[3]));
        }

        *(float4*)(out_depth + p) = make_float4(res[0], res[1], res[2], res[3]);
    }
}

// ---------------------------------------------------------------------------
extern "C" void kernel_launch(void* const* d_in, const int* in_sizes, int n_in,
                              void* d_out, int out_size)
{
    const float* r   = (const float*)d_in[0];
    const float* w   = (const float*)d_in[1];
    const float* Jp  = (const float*)d_in[2];
    const float* Jd  = (const float*)d_in[3];
    const float* lam = (const float*)d_in[4];
    float* out = (float*)d_out;

    dba_kernel<<<GRID, TPB>>>(r, w, Jp, Jd, lam, out);
}

// round 14
// speedup vs baseline: 1.4377x; 1.0224x over previous
#include <cuda_runtime.h>
#include <cuda_fp16.h>
#include <math.h>

#define B_DIM  16
#define N_DIM  196608
#define TPB    256
#define NSLICE 24                 // blocks per batch: 196608/(24*256)=32 exact
#define GRID   (B_DIM * NSLICE)   // 384 blocks; <= 3 CTA/SM * 148 = 444 resident
#define NACC   27                 // 21 sym H entries + 6 g entries
#define QPB    (N_DIM / 4)        // depth quads per batch = 49152

// Fixed-slot partials: [value 0..26][batch][slice]
__device__ float g_part[NACC * B_DIM * NSLICE];

// per-batch barrier state (generation monotonic across graph replays)
__device__ unsigned int g_bcnt[B_DIM];
__device__ volatile unsigned int g_bgen[B_DIM];

#define SP ((size_t)B_DIM * N_DIM)
// half2 scratch: plane k holds (ih[2k], ih[2k+1]) per point
__device__ __align__(16) __half2 g_scrh[3 * B_DIM * N_DIM];
// half scratch: inv*gd per point (error is proportional to value -> rel ~5e-4)
__device__ __align__(16) __half  g_scrf[B_DIM * N_DIM];

// ---------------------------------------------------------------------------
// Per-batch barrier: only the NSLICE blocks of one batch synchronize.
// Generation read BEFORE arrive; last arriver resets count and bumps gen.
// All blocks resident (GRID=384 <= 444 capacity) -> no deadlock.
// ---------------------------------------------------------------------------
__device__ __forceinline__ void batch_barrier(int b)
{
    __syncthreads();
    if (threadIdx.x == 0) {
        const unsigned int my = g_bgen[b];   // volatile read, before arrive
        __threadfence();
        const unsigned int prev = atomicAdd(&g_bcnt[b], 1u);
        if (prev == NSLICE - 1) {
            g_bcnt[b] = 0;
            __threadfence();
            g_bgen[b] = my + 1;              // release
        } else {
            while (g_bgen[b] == my) { __nanosleep(64); }
        }
        __threadfence();
    }
    __syncthreads();
}

// ---------------------------------------------------------------------------
// Single fused kernel: reduce -> per-batch barrier -> redundant solve -> depth
// ---------------------------------------------------------------------------
__global__ void __launch_bounds__(TPB, 3) dba_kernel(
    const float* __restrict__ r, const float* __restrict__ w,
    const float* __restrict__ Jp, const float* __restrict__ Jd,
    const float* __restrict__ lmbda, float* __restrict__ out)
{
    const int b     = blockIdx.x / NSLICE;
    const int slice = blockIdx.x % NSLICE;
    const float lam = __ldg(lmbda + b);

    float* __restrict__ out_pose  = out;
    float* __restrict__ out_depth = out + B_DIM * 6;

    // ===================== Phase 1: streaming reduction =====================
    float acc[NACC];
#pragma unroll
    for (int i = 0; i < NACC; i++) acc[i] = 0.f;

    const size_t base = (size_t)b * N_DIM;

    // exactly 32 iterations per thread (no ragged tail)
    for (int n = slice * TPB + threadIdx.x; n < N_DIM; n += NSLICE * TPB) {
        const size_t p = base + (size_t)n;
        const float2 rv = *(const float2*)(r  + 2 * p);
        const float2 wv = *(const float2*)(w  + 2 * p);
        const float2 jd = *(const float2*)(Jd + 2 * p);
        const float4 a0 = *(const float4*)(Jp + 12 * p);
        const float4 a1 = *(const float4*)(Jp + 12 * p + 4);
        const float4 a2 = *(const float4*)(Jp + 12 * p + 8);
        const float jp0[6] = {a0.x, a0.y, a0.z, a0.w, a1.x, a1.y};
        const float jp1[6] = {a1.z, a1.w, a2.x, a2.y, a2.z, a2.w};

        const float conf = wv.x;
        const float nl   = wv.y;

        float hpd[6];
#pragma unroll
        for (int i = 0; i < 6; i++)
            hpd[i] = conf * fmaf(jd.x, jp0[i], jd.y * jp1[i]);

        const float hdd = conf * fmaf(jd.x, jd.x, jd.y * jd.y);
        const float gd  = conf * fmaf(jd.x, rv.x, jd.y * rv.y);
        const float inv = 1.0f / fmaxf(hdd + lam + nl, 1e-4f);

        float cj0[6], cj1[6], ih[6];
#pragma unroll
        for (int i = 0; i < 6; i++) {
            cj0[i] = conf * jp0[i];
            cj1[i] = conf * jp1[i];
            ih[i]  = inv * hpd[i];
        }

        // scratch for depth pass (warp-dense)
        g_scrh[0 * SP + p] = __floats2half2_rn(ih[0], ih[1]);
        g_scrh[1 * SP + p] = __floats2half2_rn(ih[2], ih[3]);
        g_scrh[2 * SP + p] = __floats2half2_rn(ih[4], ih[5]);
        g_scrf[p] = __float2half_rn(inv * gd);

        int idx = 0;
#pragma unroll
        for (int i = 0; i < 6; i++) {
#pragma unroll
            for (int j = i; j < 6; j++) {
                float t = acc[idx];
                t = fmaf(cj0[i], jp0[j], t);
                t = fmaf(cj1[i], jp1[j], t);
                t = fmaf(-ih[i], hpd[j], t);
                acc[idx++] = t;
            }
        }
#pragma unroll
        for (int i = 0; i < 6; i++) {
            float t = acc[21 + i];
            t = fmaf(cj0[i], rv.x, t);
            t = fmaf(cj1[i], rv.y, t);
            t = fmaf(-ih[i], gd, t);
            acc[21 + i] = t;
        }
    }

    // block-level reduce
#pragma unroll
    for (int off = 16; off; off >>= 1) {
#pragma unroll
        for (int i = 0; i < NACC; i++)
            acc[i] += __shfl_down_sync(0xFFFFFFFFu, acc[i], off);
    }

    __shared__ float sh[TPB / 32][NACC];
    const int wid  = threadIdx.x >> 5;
    const int lane = threadIdx.x & 31;
    if (lane == 0) {
#pragma unroll
        for (int i = 0; i < NACC; i++) sh[wid][i] = acc[i];
    }
    __syncthreads();

    if (threadIdx.x < NACC) {
        float s = 0.f;
#pragma unroll
        for (int wgi = 0; wgi < TPB / 32; wgi++) s += sh[wgi][threadIdx.x];
        g_part[threadIdx.x * (B_DIM * NSLICE) + b * NSLICE + slice] = s;
    }

    batch_barrier(b);

    // ========== Phase 2: redundant per-block final reduce + LU solve ========
    __shared__ float sums[NACC];
    __shared__ float dpsh[6];
    if (threadIdx.x < NACC) {
        const float* pp = g_part + threadIdx.x * (B_DIM * NSLICE) + b * NSLICE;
        float t = 0.f;
#pragma unroll
        for (int i = 0; i < NSLICE; i++) t += pp[i];
        sums[threadIdx.x] = t;
    }
    __syncthreads();

    if (threadIdx.x == 0) {
        float M[6][6], gv[6], x[6];
        int idx = 0;
        for (int i = 0; i < 6; i++)
            for (int j = i; j < 6; j++) {
                const float v = sums[idx++];
                M[i][j] = v; M[j][i] = v;
            }
        const float dd = lam + 0.011f;
        for (int i = 0; i < 6; i++) M[i][i] += dd;
        for (int i = 0; i < 6; i++) gv[i] = sums[21 + i];

        for (int c = 0; c < 6; c++) {
            int piv = c; float mx = fabsf(M[c][c]);
            for (int rr = c + 1; rr < 6; rr++) {
                const float a = fabsf(M[rr][c]);
                if (a > mx) { mx = a; piv = rr; }
            }
            if (piv != c) {
                for (int j = 0; j < 6; j++) {
                    const float tmp = M[c][j]; M[c][j] = M[piv][j]; M[piv][j] = tmp;
                }
                const float tmp = gv[c]; gv[c] = gv[piv]; gv[piv] = tmp;
            }
            float d = M[c][c];
            if (d == 0.f) d = 1e-30f;
            const float invd = 1.0f / d;
            for (int rr = c + 1; rr < 6; rr++) {
                const float f = M[rr][c] * invd;
                for (int j = c; j < 6; j++) M[rr][j] -= f * M[c][j];
                gv[rr] -= f * gv[c];
            }
        }
        for (int i = 5; i >= 0; i--) {
            float s = gv[i];
            for (int j = i + 1; j < 6; j++) s -= M[i][j] * x[j];
            x[i] = s / M[i][i];
        }

#pragma unroll
        for (int i = 0; i < 6; i++) dpsh[i] = x[i];   // unclipped, for depth
        if (slice == 0) {
            for (int i = 0; i < 6; i++)
                out_pose[b * 6 + i] = fminf(fmaxf(x[i], -2.0f), 2.0f);
        }
    }
    __syncthreads();

    float2 dpp[3];
#pragma unroll
    for (int k = 0; k < 3; k++) {
        dpp[k].x = dpsh[2 * k];
        dpp[k].y = dpsh[2 * k + 1];
    }

    // ===================== Phase 3: depth (own batch only) ==================
    // exactly 8 iterations per thread
    for (int i = slice * TPB + threadIdx.x; i < QPB; i += NSLICE * TPB) {
        const size_t p = base + (size_t)i * 4;

        const uint2 fg = *(const uint2*)(g_scrf + p);   // 4x half inv*gd
        const uint4 u0 = *(const uint4*)(g_scrh + 0 * SP + p);
        const uint4 u1 = *(const uint4*)(g_scrh + 1 * SP + p);
        const uint4 u2 = *(const uint4*)(g_scrh + 2 * SP + p);

        const float2 g01 = __half22float2(*(const __half2*)&fg.x);
        const float2 g23 = __half22float2(*(const __half2*)&fg.y);
        float res[4] = {g01.x, g01.y, g23.x, g23.y};

        const uint4 uu[3] = {u0, u1, u2};
#pragma unroll
        for (int k = 0; k < 3; k++) {
            const float2 q0 = __half22float2(*(const __half2*)&uu[k].x);
            const float2 q1 = __half22float2(*(const __half2*)&uu[k].y);
            const float2 q2 = __half22float2(*(const __half2*)&uu[k].z);
            const float2 q3 = __half22float2(*(const __half2*)&uu[k].w);
            res[0] = fmaf(-q0.x, dpp[k].x, fmaf(-q0.y, dpp[k].y, res[0]));
            res[1] = fmaf(-q1.x, dpp[k].x, fmaf(-q1.y, dpp[k].y, res[1]));
            res[2] = fmaf(-q2.x, dpp[k].x, fmaf(-q2.y, dpp[k].y, res[2]));
            res[3] = fmaf(-q3.x, dpp[k].x, fmaf(-q3.y, dpp[k].y, res[3]));
        }

        *(float4*)(out_depth + p) = make_float4(res[0], res[1], res[2], res[3]);
    }
}

// ---------------------------------------------------------------------------
extern "C" void kernel_launch(void* const* d_in, const int* in_sizes, int n_in,
                              void* d_out, int out_size)
{
    const float* r   = (const float*)d_in[0];
    const float* w   = (const float*)d_in[1];
    const float* Jp  = (const float*)d_in[2];
    const float* Jd  = (const float*)d_in[3];
    const float* lam = (const float*)d_in[4];
    float* out = (float*)d_out;

    dba_kernel<<<GRID, TPB>>>(r, w, Jp, Jd, lam, out);
}